// round 5
// baseline (speedup 1.0000x reference)
#include <cuda_runtime.h>
#include <cuda_bf16.h>
#include <math.h>
#include <float.h>
#include <stdint.h>

// ---------------- problem dims ----------------
#define NB   2048
#define VV   50000
#define E1   1024
#define E2   512
#define CC   2
#define KK   200
#define EMB  300

#define KP   50048              // VV padded to multiple of 64
#define G1NT (KP / 64)          // 782 k-tiles

// ---------------- float scratch ----------------------------------------------
#define OFF_EN1    0LL
#define OFF_EN2    (OFF_EN1 + (long long)NB*E1)
#define OFF_PM     (OFF_EN2 + (long long)NB*E2)
#define OFF_LV     (OFF_PM + (long long)NB*CC)
#define OFF_Z      (OFF_LV + (long long)NB*CC)
#define OFF_ZX     (OFF_Z + (long long)NB*CC)
#define OFF_ZC     (OFF_ZX + (long long)NB*CC)
#define OFF_THETA  (OFF_ZC + (long long)KK*CC)
#define OFF_MU1    (OFF_THETA + (long long)NB*KK)
#define OFF_MU2    (OFF_MU1 + (long long)KK*100)
#define OFF_MUZ    (OFF_MU2 + (long long)KK*100)
#define OFF_LOGITS (OFF_MUZ + (long long)KK*EMB)
#define OFF_BETA   (OFF_LOGITS + (long long)KK*VV)
#define OFF_SPM    (OFF_BETA + (long long)KK*VV)
#define OFF_SLV    (OFF_SPM + 4)
#define OFF_SZ     (OFF_SLV + 4)
#define OFF_ST     (OFF_SZ + 4)
#define SCRATCH_FLOATS (OFF_ST + 8)

__device__ float g_scratch[SCRATCH_FLOATS];

// ---------------- int8 quantized planes --------------------------------------
#define QA1_OFF 0LL
#define QA2_OFF (QA1_OFF + (long long)NB * KP)
#define QB1_OFF (QA2_OFF + (long long)NB * KP)
#define QB2_OFF (QB1_OFF + (long long)E1 * KP)
#define Q_TOTAL (QB2_OFF + (long long)E1 * KP)

__device__ __align__(16) char g_q[Q_TOTAL];
__device__ float g_sA[NB];
__device__ float g_sB[E1];

__device__ __forceinline__ float softplusf(float x) {
    return fmaxf(x, 0.0f) + log1pf(expf(-fabsf(x)));
}

__device__ __forceinline__ uint32_t pack4(int a, int b, int c, int d) {
    uint32_t lo = __byte_perm((uint32_t)a, (uint32_t)b, 0x0040);
    uint32_t hi = __byte_perm((uint32_t)c, (uint32_t)d, 0x0040);
    return __byte_perm(lo, hi, 0x5410);
}

// =============================================================================
// Pre-pass: per-row 2-digit s8 quantization of A=input (2048 rows) and
// B=en1_W (1024 rows). x = s*(c1 + c2/256 + r), |r| <= s/512.
// =============================================================================
__global__ void __launch_bounds__(256)
quantize_rows(const float* __restrict__ A, const float* __restrict__ B)
{
    __shared__ float red[256];
    const int b = blockIdx.x, tid = threadIdx.x;
    const float* src;
    char *d1, *d2;
    float* sout;
    if (b < NB) {
        src = A + (size_t)b * VV;
        d1 = g_q + QA1_OFF + (size_t)b * KP;
        d2 = g_q + QA2_OFF + (size_t)b * KP;
        sout = &g_sA[b];
    } else {
        int r = b - NB;
        src = B + (size_t)r * VV;
        d1 = g_q + QB1_OFF + (size_t)r * KP;
        d2 = g_q + QB2_OFF + (size_t)r * KP;
        sout = &g_sB[r];
    }

    // pass 1: row max |x|
    float mx = 0.f;
    for (int i = tid; i < VV / 4; i += 256) {
        float4 v = *reinterpret_cast<const float4*>(src + i * 4);
        mx = fmaxf(mx, fmaxf(fmaxf(fabsf(v.x), fabsf(v.y)),
                             fmaxf(fabsf(v.z), fabsf(v.w))));
    }
    red[tid] = mx;
    __syncthreads();
    for (int st = 128; st > 0; st >>= 1) {
        if (tid < st) red[tid] = fmaxf(red[tid], red[tid + st]);
        __syncthreads();
    }
    const float maxv = red[0];
    const float inv = (maxv > 0.f) ? 126.5f / maxv : 0.f;
    if (tid == 0) *sout = (maxv > 0.f) ? maxv / 126.5f : 0.f;

    // pass 2: quantize
    uint32_t* w1 = reinterpret_cast<uint32_t*>(d1);
    uint32_t* w2 = reinterpret_cast<uint32_t*>(d2);
    for (int i = tid; i < VV / 4; i += 256) {
        float4 v = *reinterpret_cast<const float4*>(src + i * 4);
        float q0 = v.x * inv, q1 = v.y * inv, q2 = v.z * inv, q3 = v.w * inv;
        float f0 = rintf(q0), f1 = rintf(q1), f2 = rintf(q2), f3 = rintf(q3);
        float r0 = fminf(fmaxf((q0 - f0) * 256.f, -127.f), 127.f);
        float r1 = fminf(fmaxf((q1 - f1) * 256.f, -127.f), 127.f);
        float r2 = fminf(fmaxf((q2 - f2) * 256.f, -127.f), 127.f);
        float r3 = fminf(fmaxf((q3 - f3) * 256.f, -127.f), 127.f);
        w1[i] = pack4((int)f0, (int)f1, (int)f2, (int)f3);
        w2[i] = pack4((int)rintf(r0), (int)rintf(r1), (int)rintf(r2), (int)rintf(r3));
    }
    // zero the pad region [VV, KP)
    if (tid < (KP - VV) / 4) {
        w1[VV / 4 + tid] = 0u;
        w2[VV / 4 + tid] = 0u;
    }
}

// =============================================================================
// GEMM1 int8 x3: en1 = softplus(sA*sB*(A1B1 + (A1B2+A2B1)/256) + bias)
// 128x128 tile, BK=64, 512 threads, 3-stage cp.async pipeline.
// smem plane: 128 rows x 80B (64B data + pad); planes A1,A2,B1,B2.
// =============================================================================
#define PL    10240
#define BUFB  (4 * PL)
#define G1_SMEM (3 * BUFB)

__device__ __forceinline__ void mma_s8(int* d,
                                       uint32_t a0, uint32_t a1, uint32_t a2, uint32_t a3,
                                       uint32_t b0, uint32_t b1)
{
    asm volatile(
        "mma.sync.aligned.m16n8k32.row.col.s32.s8.s8.s32 "
        "{%0,%1,%2,%3},{%4,%5,%6,%7},{%8,%9},{%0,%1,%2,%3};"
        : "+r"(d[0]), "+r"(d[1]), "+r"(d[2]), "+r"(d[3])
        : "r"(a0), "r"(a1), "r"(a2), "r"(a3), "r"(b0), "r"(b1));
}

__global__ void __launch_bounds__(512, 1)
gemm1_i8(const float* __restrict__ bias, float* __restrict__ C)
{
    extern __shared__ __align__(16) char sm[];
    const uint32_t sb32 = (uint32_t)__cvta_generic_to_shared(sm);
    const int tid = threadIdx.x;
    const int lane = tid & 31, warp = tid >> 5;
    const int gid = lane >> 2, tig = lane & 3;
    const int wm = warp >> 2, wn = warp & 3;
    const int m0 = blockIdx.y * 128, n0 = blockIdx.x * 128;

    int acch[2][4][4], accm[2][4][4];
#pragma unroll
    for (int i = 0; i < 2; i++)
#pragma unroll
        for (int j = 0; j < 4; j++)
#pragma unroll
            for (int l = 0; l < 4; l++) { acch[i][j][l] = 0; accm[i][j][l] = 0; }

    const int row = tid >> 2, part = tid & 3;
    const char* gA1 = g_q + QA1_OFF + (size_t)(m0 + row) * KP + part * 16;
    const char* gA2 = g_q + QA2_OFF + (size_t)(m0 + row) * KP + part * 16;
    const char* gB1 = g_q + QB1_OFF + (size_t)(n0 + row) * KP + part * 16;
    const char* gB2 = g_q + QB2_OFF + (size_t)(n0 + row) * KP + part * 16;
    const uint32_t sdst = sb32 + (uint32_t)(row * 80 + part * 16);

    auto issue = [&](int t) {
        const uint32_t boff = (uint32_t)(t % 3) * BUFB;
        const size_t k = (size_t)t * 64;
        asm volatile("cp.async.ca.shared.global [%0], [%1], 16;"
                     :: "r"(sdst + boff), "l"(gA1 + k) : "memory");
        asm volatile("cp.async.ca.shared.global [%0], [%1], 16;"
                     :: "r"(sdst + boff + PL), "l"(gA2 + k) : "memory");
        asm volatile("cp.async.ca.shared.global [%0], [%1], 16;"
                     :: "r"(sdst + boff + 2 * PL), "l"(gB1 + k) : "memory");
        asm volatile("cp.async.ca.shared.global [%0], [%1], 16;"
                     :: "r"(sdst + boff + 3 * PL), "l"(gB2 + k) : "memory");
        asm volatile("cp.async.commit_group;" ::: "memory");
    };

    issue(0);
    issue(1);

    for (int t = 0; t < G1NT; t++) {
        if (t == G1NT - 1) asm volatile("cp.async.wait_group 0;" ::: "memory");
        else               asm volatile("cp.async.wait_group 1;" ::: "memory");
        __syncthreads();
        if (t + 2 < G1NT) issue(t + 2);

        const char* bb = sm + (size_t)(t % 3) * BUFB;
#pragma unroll
        for (int ks = 0; ks < 2; ks++) {
            const int ko = ks * 32 + tig * 4;
            uint32_t a1[2][4], a2[2][4], b1[4][2], b2[4][2];
#pragma unroll
            for (int ms = 0; ms < 2; ms++) {
                const char* p = bb + (wm * 32 + ms * 16 + gid) * 80 + ko;
                a1[ms][0] = *(const uint32_t*)(p);
                a1[ms][1] = *(const uint32_t*)(p + 8 * 80);
                a1[ms][2] = *(const uint32_t*)(p + 16);
                a1[ms][3] = *(const uint32_t*)(p + 8 * 80 + 16);
                a2[ms][0] = *(const uint32_t*)(p + PL);
                a2[ms][1] = *(const uint32_t*)(p + PL + 8 * 80);
                a2[ms][2] = *(const uint32_t*)(p + PL + 16);
                a2[ms][3] = *(const uint32_t*)(p + PL + 8 * 80 + 16);
            }
#pragma unroll
            for (int ns = 0; ns < 4; ns++) {
                const char* p = bb + 2 * PL + (wn * 32 + ns * 8 + gid) * 80 + ko;
                b1[ns][0] = *(const uint32_t*)(p);
                b1[ns][1] = *(const uint32_t*)(p + 16);
                b2[ns][0] = *(const uint32_t*)(p + PL);
                b2[ns][1] = *(const uint32_t*)(p + PL + 16);
            }
#pragma unroll
            for (int ms = 0; ms < 2; ms++)
#pragma unroll
                for (int ns = 0; ns < 4; ns++) {
                    mma_s8(acch[ms][ns], a1[ms][0], a1[ms][1], a1[ms][2], a1[ms][3],
                           b1[ns][0], b1[ns][1]);
                    mma_s8(accm[ms][ns], a1[ms][0], a1[ms][1], a1[ms][2], a1[ms][3],
                           b2[ns][0], b2[ns][1]);
                    mma_s8(accm[ms][ns], a2[ms][0], a2[ms][1], a2[ms][2], a2[ms][3],
                           b1[ns][0], b1[ns][1]);
                }
        }
    }

    // epilogue: combine digits, scale, bias, softplus
#pragma unroll
    for (int ms = 0; ms < 2; ms++) {
        const int r0 = m0 + wm * 32 + ms * 16 + gid;
        const float sa0 = g_sA[r0], sa8 = g_sA[r0 + 8];
#pragma unroll
        for (int ns = 0; ns < 4; ns++) {
            const int c0 = n0 + wn * 32 + ns * 8 + 2 * tig;
            const float sc0 = g_sB[c0], sc1 = g_sB[c0 + 1];
            const float bv0 = bias[c0], bv1 = bias[c0 + 1];
            float v00 = sa0 * sc0 * ((float)acch[ms][ns][0] + (float)accm[ms][ns][0] * 0.00390625f) + bv0;
            float v01 = sa0 * sc1 * ((float)acch[ms][ns][1] + (float)accm[ms][ns][1] * 0.00390625f) + bv1;
            float v10 = sa8 * sc0 * ((float)acch[ms][ns][2] + (float)accm[ms][ns][2] * 0.00390625f) + bv0;
            float v11 = sa8 * sc1 * ((float)acch[ms][ns][3] + (float)accm[ms][ns][3] * 0.00390625f) + bv1;
            C[(size_t)r0 * E1 + c0]           = softplusf(v00);
            C[(size_t)r0 * E1 + c0 + 1]       = softplusf(v01);
            C[(size_t)(r0 + 8) * E1 + c0]     = softplusf(v10);
            C[(size_t)(r0 + 8) * E1 + c0 + 1] = softplusf(v11);
        }
    }
}

// ============================ bf16x3 NT GEMM (en2 + logits) ==================
__device__ __forceinline__ uint32_t pk_bf16(float lo, float hi) {
    uint32_t r;
    asm("cvt.rn.bf16x2.f32 %0, %1, %2;" : "=r"(r) : "f"(hi), "f"(lo));
    return r;
}

__device__ __forceinline__ void mma_bf16(float* d,
                                         uint32_t a0, uint32_t a1, uint32_t a2, uint32_t a3,
                                         uint32_t b0, uint32_t b1)
{
    asm volatile(
        "mma.sync.aligned.m16n8k16.row.col.f32.bf16.bf16.f32 "
        "{%0,%1,%2,%3},{%4,%5,%6,%7},{%8,%9},{%0,%1,%2,%3};"
        : "+f"(d[0]), "+f"(d[1]), "+f"(d[2]), "+f"(d[3])
        : "r"(a0), "r"(a1), "r"(a2), "r"(a3), "r"(b0), "r"(b1));
}

#define NTB_SMEM (2 * 10240 * 4)

template<bool SP, bool HB, bool CHKMN>
__global__ void __launch_bounds__(512, 1)
gemm_nt_bf16x3(const float* __restrict__ A, const float* __restrict__ B,
               const float* __restrict__ bias, float* __restrict__ C,
               int M, int N, int K)
{
    extern __shared__ __align__(16) uint32_t sw[];
    const int tid = threadIdx.x;
    const int lane = tid & 31, warp = tid >> 5;
    const int gid = lane >> 2, tig = lane & 3;
    const int wm = warp >> 2, wn = warp & 3;
    const int m0 = blockIdx.y * 128, n0 = blockIdx.x * 128;
    const int nt = (K + 31) / 32;

    float acc[2][4][4];
#pragma unroll
    for (int i = 0; i < 2; i++)
#pragma unroll
        for (int j = 0; j < 4; j++)
#pragma unroll
            for (int l = 0; l < 4; l++) acc[i][j][l] = 0.0f;

    const int srow = tid >> 3;
    const int sq   = tid & 7;
    float4 stA[2], stB[2];

    auto load_tile = [&](int t) {
        const int gk = t * 32 + sq * 4;
#pragma unroll
        for (int l = 0; l < 2; l++) {
            int r = srow + l * 64;
            {
                int gm = m0 + r;
                float4 v = make_float4(0.f, 0.f, 0.f, 0.f);
                if (((!CHKMN) || gm < M)) {
                    if (gk + 3 < K) v = *reinterpret_cast<const float4*>(A + (size_t)gm * K + gk);
                    else if (gk < K) {
                        const float* p = A + (size_t)gm * K;
                        v.x = p[gk];
                        if (gk + 1 < K) v.y = p[gk + 1];
                        if (gk + 2 < K) v.z = p[gk + 2];
                    }
                }
                stA[l] = v;
            }
            {
                int gn = n0 + r;
                float4 v = make_float4(0.f, 0.f, 0.f, 0.f);
                if (((!CHKMN) || gn < N)) {
                    if (gk + 3 < K) v = *reinterpret_cast<const float4*>(B + (size_t)gn * K + gk);
                    else if (gk < K) {
                        const float* p = B + (size_t)gn * K;
                        v.x = p[gk];
                        if (gk + 1 < K) v.y = p[gk + 1];
                        if (gk + 2 < K) v.z = p[gk + 2];
                    }
                }
                stB[l] = v;
            }
        }
    };

    auto store_tile = [&](uint32_t* buf) {
#pragma unroll
        for (int l = 0; l < 2; l++) {
            int r = srow + l * 64;
            uint32_t w = (uint32_t)(r * 20 + sq * 2);
            {
                float4 v = stA[l];
                __nv_bfloat16 hx = __float2bfloat16_rn(v.x), hy = __float2bfloat16_rn(v.y);
                __nv_bfloat16 hz = __float2bfloat16_rn(v.z), hw = __float2bfloat16_rn(v.w);
                buf[w]     = ((uint32_t)__bfloat16_as_ushort(hy) << 16) | __bfloat16_as_ushort(hx);
                buf[w + 1] = ((uint32_t)__bfloat16_as_ushort(hw) << 16) | __bfloat16_as_ushort(hz);
                buf[w + 2560]     = pk_bf16(v.x - __bfloat162float(hx), v.y - __bfloat162float(hy));
                buf[w + 2560 + 1] = pk_bf16(v.z - __bfloat162float(hz), v.w - __bfloat162float(hw));
            }
            {
                float4 v = stB[l];
                __nv_bfloat16 hx = __float2bfloat16_rn(v.x), hy = __float2bfloat16_rn(v.y);
                __nv_bfloat16 hz = __float2bfloat16_rn(v.z), hw = __float2bfloat16_rn(v.w);
                buf[w + 5120]     = ((uint32_t)__bfloat16_as_ushort(hy) << 16) | __bfloat16_as_ushort(hx);
                buf[w + 5120 + 1] = ((uint32_t)__bfloat16_as_ushort(hw) << 16) | __bfloat16_as_ushort(hz);
                buf[w + 7680]     = pk_bf16(v.x - __bfloat162float(hx), v.y - __bfloat162float(hy));
                buf[w + 7680 + 1] = pk_bf16(v.z - __bfloat162float(hz), v.w - __bfloat162float(hw));
            }
        }
    };

    load_tile(0);
    store_tile(sw);
    __syncthreads();

    for (int t = 0; t < nt; t++) {
        const int b = t & 1;
        uint32_t* bb = sw + b * 10240;
        if (t + 1 < nt) load_tile(t + 1);

#pragma unroll
        for (int kkw = 0; kkw < 16; kkw += 8) {
            uint32_t ah[2][4], al[2][4], bh[4][2], bl[4][2];
#pragma unroll
            for (int ms = 0; ms < 2; ms++) {
                int base = (wm * 32 + ms * 16 + gid) * 20 + kkw + tig;
                ah[ms][0] = bb[base];       ah[ms][1] = bb[base + 160];
                ah[ms][2] = bb[base + 4];   ah[ms][3] = bb[base + 164];
                al[ms][0] = bb[base + 2560];       al[ms][1] = bb[base + 2560 + 160];
                al[ms][2] = bb[base + 2560 + 4];   al[ms][3] = bb[base + 2560 + 164];
            }
#pragma unroll
            for (int ns = 0; ns < 4; ns++) {
                int base = 5120 + (wn * 32 + ns * 8 + gid) * 20 + kkw + tig;
                bh[ns][0] = bb[base];       bh[ns][1] = bb[base + 4];
                bl[ns][0] = bb[base + 2560]; bl[ns][1] = bb[base + 2560 + 4];
            }
#pragma unroll
            for (int ms = 0; ms < 2; ms++)
#pragma unroll
                for (int ns = 0; ns < 4; ns++) {
                    mma_bf16(acc[ms][ns], ah[ms][0], ah[ms][1], ah[ms][2], ah[ms][3],
                             bh[ns][0], bh[ns][1]);
                    mma_bf16(acc[ms][ns], ah[ms][0], ah[ms][1], ah[ms][2], ah[ms][3],
                             bl[ns][0], bl[ns][1]);
                    mma_bf16(acc[ms][ns], al[ms][0], al[ms][1], al[ms][2], al[ms][3],
                             bh[ns][0], bh[ns][1]);
                }
        }

        if (t + 1 < nt) store_tile(sw + (b ^ 1) * 10240);
        __syncthreads();
    }

#pragma unroll
    for (int ms = 0; ms < 2; ms++) {
        int r0 = m0 + wm * 32 + ms * 16 + gid;
#pragma unroll
        for (int ns = 0; ns < 4; ns++) {
            int c0 = n0 + wn * 32 + ns * 8 + 2 * tig;
            float bv0 = 0.f, bv1 = 0.f;
            if (HB) { bv0 = bias[c0]; bv1 = bias[c0 + 1]; }
            float v00 = acc[ms][ns][0] + bv0;
            float v01 = acc[ms][ns][1] + bv1;
            float v10 = acc[ms][ns][2] + bv0;
            float v11 = acc[ms][ns][3] + bv1;
            if (SP) { v00 = softplusf(v00); v01 = softplusf(v01);
                      v10 = softplusf(v10); v11 = softplusf(v11); }
            if (!CHKMN) {
                C[(size_t)r0 * N + c0]           = v00;
                C[(size_t)r0 * N + c0 + 1]       = v01;
                C[(size_t)(r0 + 8) * N + c0]     = v10;
                C[(size_t)(r0 + 8) * N + c0 + 1] = v11;
            } else {
                if (r0 < M) {
                    if (c0 < N)     C[(size_t)r0 * N + c0]     = v00;
                    if (c0 + 1 < N) C[(size_t)r0 * N + c0 + 1] = v01;
                }
                if (r0 + 8 < M) {
                    if (c0 < N)     C[(size_t)(r0 + 8) * N + c0]     = v10;
                    if (c0 + 1 < N) C[(size_t)(r0 + 8) * N + c0 + 1] = v11;
                }
            }
        }
    }
}

// ============================ tf32 recon =====================================
__device__ __forceinline__ unsigned tf32_rna(float x) {
    unsigned r;
    asm("cvt.rna.tf32.f32 %0, %1;" : "=r"(r) : "f"(x));
    return r;
}

__device__ __forceinline__ void mma_tf32(float* d,
                                         unsigned a0, unsigned a1, unsigned a2, unsigned a3,
                                         unsigned b0, unsigned b1)
{
    asm volatile(
        "mma.sync.aligned.m16n8k8.row.col.f32.tf32.tf32.f32 "
        "{%0,%1,%2,%3},{%4,%5,%6,%7},{%8,%9},{%0,%1,%2,%3};"
        : "+f"(d[0]), "+f"(d[1]), "+f"(d[2]), "+f"(d[3])
        : "r"(a0), "r"(a1), "r"(a2), "r"(a3), "r"(b0), "r"(b1));
}

__global__ void __launch_bounds__(256, 2)
recon_tf32(const float* __restrict__ A, const float* __restrict__ B,
           float* __restrict__ C)
{
    __shared__ float Ah[128][20];
    __shared__ float Bh[16][136];
    const int tid = threadIdx.x;
    const int lane = tid & 31, warp = tid >> 5;
    const int gid = lane >> 2, tig = lane & 3;
    const int wm = warp >> 1, wn = warp & 1;
    const int m0 = blockIdx.y * 128;
    const int n0 = blockIdx.x * 128;

    float acc[2][8][4];
#pragma unroll
    for (int i = 0; i < 2; i++)
#pragma unroll
        for (int j = 0; j < 8; j++)
#pragma unroll
            for (int l = 0; l < 4; l++) acc[i][j][l] = 0.0f;

    for (int k0 = 0; k0 < KK; k0 += 16) {
#pragma unroll
        for (int l = 0; l < 2; l++) {
            int idx = tid + l * 256;
            int row = idx >> 2, kq = (idx & 3) * 4;
            int gk = k0 + kq;
            float4 v = make_float4(0.f, 0.f, 0.f, 0.f);
            if (gk + 3 < KK)
                v = *reinterpret_cast<const float4*>(A + (size_t)(m0 + row) * KK + gk);
            Ah[row][kq + 0] = __uint_as_float(tf32_rna(v.x));
            Ah[row][kq + 1] = __uint_as_float(tf32_rna(v.y));
            Ah[row][kq + 2] = __uint_as_float(tf32_rna(v.z));
            Ah[row][kq + 3] = __uint_as_float(tf32_rna(v.w));
        }
#pragma unroll
        for (int l = 0; l < 2; l++) {
            int idx = tid + l * 256;
            int kk = idx >> 5, nc = (idx & 31) * 4;
            int gk = k0 + kk, gn = n0 + nc;
            float4 v = make_float4(0.f, 0.f, 0.f, 0.f);
            if (gk < KK && gn + 3 < VV)
                v = *reinterpret_cast<const float4*>(B + (size_t)gk * VV + gn);
            Bh[kk][nc + 0] = __uint_as_float(tf32_rna(v.x));
            Bh[kk][nc + 1] = __uint_as_float(tf32_rna(v.y));
            Bh[kk][nc + 2] = __uint_as_float(tf32_rna(v.z));
            Bh[kk][nc + 3] = __uint_as_float(tf32_rna(v.w));
        }
        __syncthreads();

#pragma unroll
        for (int kk = 0; kk < 16; kk += 8) {
            unsigned a[2][4], b[8][2];
#pragma unroll
            for (int ms = 0; ms < 2; ms++) {
                int r = wm * 32 + ms * 16 + gid;
                a[ms][0] = __float_as_uint(Ah[r][kk + tig]);
                a[ms][1] = __float_as_uint(Ah[r + 8][kk + tig]);
                a[ms][2] = __float_as_uint(Ah[r][kk + tig + 4]);
                a[ms][3] = __float_as_uint(Ah[r + 8][kk + tig + 4]);
            }
#pragma unroll
            for (int ns = 0; ns < 8; ns++) {
                int n = wn * 64 + ns * 8 + gid;
                b[ns][0] = __float_as_uint(Bh[kk + tig][n]);
                b[ns][1] = __float_as_uint(Bh[kk + tig + 4][n]);
            }
#pragma unroll
            for (int ms = 0; ms < 2; ms++)
#pragma unroll
                for (int ns = 0; ns < 8; ns++)
                    mma_tf32(acc[ms][ns], a[ms][0], a[ms][1], a[ms][2], a[ms][3],
                             b[ns][0], b[ns][1]);
        }
        __syncthreads();
    }

#pragma unroll
    for (int ms = 0; ms < 2; ms++) {
        int r0 = m0 + wm * 32 + ms * 16 + gid;
#pragma unroll
        for (int ns = 0; ns < 8; ns++) {
            int c0 = n0 + wn * 64 + ns * 8 + 2 * tig;
            if (c0 < VV) {
                C[(size_t)r0 * VV + c0]       = acc[ms][ns][0];
                C[(size_t)(r0 + 8) * VV + c0] = acc[ms][ns][2];
            }
            if (c0 + 1 < VV) {
                C[(size_t)r0 * VV + c0 + 1]       = acc[ms][ns][1];
                C[(size_t)(r0 + 8) * VV + c0 + 1] = acc[ms][ns][3];
            }
        }
    }
}

// ---------------- mean / logvar heads ---------------------------------------
__global__ void meanlogvar_kernel(const float* __restrict__ en2,
                                  const float* __restrict__ mW, const float* __restrict__ mb,
                                  const float* __restrict__ lW, const float* __restrict__ lb,
                                  float* __restrict__ pm, float* __restrict__ lv)
{
    int t = blockIdx.x * blockDim.x + threadIdx.x;
    if (t >= NB * 4) return;
    int n = t >> 2, j = t & 3;
    const float* w = (j < 2) ? (mW + j * E2) : (lW + (j - 2) * E2);
    const float* x = en2 + (size_t)n * E2;
    float s = 0.f;
    for (int i = 0; i < E2; i += 4) {
        float4 xa = *reinterpret_cast<const float4*>(x + i);
        float4 wa = *reinterpret_cast<const float4*>(w + i);
        s += xa.x * wa.x + xa.y * wa.y + xa.z * wa.z + xa.w * wa.w;
    }
    if (j < 2) pm[n * 2 + j] = s + mb[j];
    else       lv[n * 2 + (j - 2)] = s + lb[j - 2];
}

// ---------------- column stats of (R x 2) -----------------------------------
__global__ void colstats_kernel(const float* __restrict__ X, int R, float* __restrict__ out)
{
    __shared__ float ss[256], s2[256];
    int c = blockIdx.x, tid = threadIdx.x;
    float s = 0.f, q = 0.f;
    for (int r = tid; r < R; r += 256) {
        float x = X[r * 2 + c];
        s += x; q += x * x;
    }
    ss[tid] = s; s2[tid] = q;
    __syncthreads();
    for (int st = 128; st > 0; st >>= 1) {
        if (tid < st) { ss[tid] += ss[tid + st]; s2[tid] += s2[tid + st]; }
        __syncthreads();
    }
    if (tid == 0) {
        float m = ss[0] / R;
        out[c] = m;
        out[2 + c] = s2[0] / R - m * m;
    }
}

// ---------------- z ----------------------------------------------------------
__global__ void z_kernel(const float* __restrict__ pm, const float* __restrict__ lv,
                         const float* __restrict__ spm, const float* __restrict__ slv,
                         const float* __restrict__ gm, const float* __restrict__ bm,
                         const float* __restrict__ gl, const float* __restrict__ bl,
                         const float* __restrict__ eps,
                         float* __restrict__ gz, float* __restrict__ outz)
{
    int idx = blockIdx.x * 256 + threadIdx.x;
    if (idx >= NB * CC) return;
    int c = idx & 1;
    float pmb = gm[c] * (pm[idx] - spm[c]) * rsqrtf(spm[2 + c] + 1e-5f) + bm[c];
    float lvb = gl[c] * (lv[idx] - slv[c]) * rsqrtf(slv[2 + c] + 1e-5f) + bl[c];
    float z = pmb + sqrtf(expf(lvb)) * eps[idx];
    gz[idx] = z;
    outz[idx] = z;
}

// ---------------- BN apply ---------------------------------------------------
__global__ void bn_apply_kernel(const float* __restrict__ X, const float* __restrict__ stats,
                                const float* __restrict__ g, const float* __restrict__ b,
                                int total, float* __restrict__ o1, float* __restrict__ o2)
{
    int idx = blockIdx.x * 256 + threadIdx.x;
    if (idx >= total) return;
    int c = idx & 1;
    float y = g[c] * (X[idx] - stats[c]) * rsqrtf(stats[2 + c] + 1e-5f) + b[c];
    o1[idx] = y;
    o2[idx] = y;
}

// ---------------- theta ------------------------------------------------------
__global__ void theta_kernel(const float* __restrict__ zx, const float* __restrict__ zc,
                             float* __restrict__ gtheta, float* __restrict__ otheta)
{
    __shared__ float sz[KK * 2];
    __shared__ float red[256];
    int n = blockIdx.x, tid = threadIdx.x;
    for (int i = tid; i < KK * 2; i += 256) sz[i] = zc[i];
    __syncthreads();
    float x0 = zx[n * 2], x1 = zx[n * 2 + 1];
    float l = -FLT_MAX;
    if (tid < KK) {
        float dx = x0 - sz[tid * 2];
        float dy = x1 - sz[tid * 2 + 1];
        l = -0.5f * (dx * dx + dy * dy);
    }
    red[tid] = l;
    __syncthreads();
    for (int st = 128; st > 0; st >>= 1) {
        if (tid < st) red[tid] = fmaxf(red[tid], red[tid + st]);
        __syncthreads();
    }
    float mx = red[0];
    __syncthreads();
    float e = (tid < KK) ? expf(l - mx) : 0.f;
    red[tid] = e;
    __syncthreads();
    for (int st = 128; st > 0; st >>= 1) {
        if (tid < st) red[tid] += red[tid + st];
        __syncthreads();
    }
    float inv = 1.f / red[0];
    if (tid < KK) {
        float th = e * inv;
        gtheta[(size_t)n * KK + tid] = th;
        otheta[(size_t)n * KK + tid] = th;
    }
}

// ---------------- decoder MLP ------------------------------------------------
__global__ void mu1_kernel(const float* __restrict__ zc, const float* __restrict__ W,
                           const float* __restrict__ b, float* __restrict__ out)
{
    int t = blockIdx.x * 256 + threadIdx.x;
    if (t >= KK * 100) return;
    int k = t / 100, j = t % 100;
    float v = zc[k * 2] * W[j * 2] + zc[k * 2 + 1] * W[j * 2 + 1] + b[j];
    out[t] = softplusf(v);
}

__global__ void mu2_kernel(const float* __restrict__ mu1, const float* __restrict__ W,
                           const float* __restrict__ b, float* __restrict__ out)
{
    __shared__ float row[100];
    int k = blockIdx.x, tid = threadIdx.x;
    if (tid < 100) row[tid] = mu1[k * 100 + tid];
    __syncthreads();
    if (tid < 100) {
        const float* w = W + tid * 100;
        float s = b[tid];
        for (int i = 0; i < 100; i++) s += row[i] * w[i];
        out[k * 100 + tid] = softplusf(s);
    }
}

__global__ void muz_kernel(const float* __restrict__ mu2, const float* __restrict__ W,
                           const float* __restrict__ b, float* __restrict__ out)
{
    __shared__ float row[100];
    int k = blockIdx.x, tid = threadIdx.x;
    if (tid < 100) row[tid] = mu2[k * 100 + tid];
    __syncthreads();
    for (int j = tid; j < EMB; j += 128) {
        const float* w = W + j * 100;
        float s = b[j];
        for (int i = 0; i < 100; i++) s += row[i] * w[i];
        out[k * EMB + j] = s;
    }
}

// ---------------- beta -------------------------------------------------------
__global__ void __launch_bounds__(1024)
beta_kernel(const float* __restrict__ logits, const float* __restrict__ bbias,
            const float* __restrict__ gdec, const float* __restrict__ bdec,
            float* __restrict__ beta)
{
    __shared__ float red[1024];
    __shared__ float red2[1024];
    const int k = blockIdx.x, tid = threadIdx.x;
    const float* row = logits + (size_t)k * VV;
    const float* bb  = bbias + (size_t)k * VV;

    float s = 0.f, q = 0.f;
    for (int v = tid; v < VV; v += 1024) { float x = row[v]; s += x; q += x * x; }
    red[tid] = s; red2[tid] = q;
    __syncthreads();
    for (int st = 512; st > 0; st >>= 1) {
        if (tid < st) { red[tid] += red[tid + st]; red2[tid] += red2[tid + st]; }
        __syncthreads();
    }
    float mean = red[0] / VV;
    float var  = red2[0] / VV - mean * mean;
    float scale = gdec[k] * rsqrtf(var + 1e-5f);
    float shift = bdec[k] - mean * scale;
    __syncthreads();

    float mx = -FLT_MAX;
    for (int v = tid; v < VV; v += 1024) {
        float y = row[v] * scale + shift + bb[v];
        mx = fmaxf(mx, y);
    }
    red[tid] = mx;
    __syncthreads();
    for (int st = 512; st > 0; st >>= 1) {
        if (tid < st) red[tid] = fmaxf(red[tid], red[tid + st]);
        __syncthreads();
    }
    mx = red[0];
    __syncthreads();

    float se = 0.f;
    for (int v = tid; v < VV; v += 1024) {
        float y = row[v] * scale + shift + bb[v];
        se += expf(y - mx);
    }
    red[tid] = se;
    __syncthreads();
    for (int st = 512; st > 0; st >>= 1) {
        if (tid < st) red[tid] += red[tid + st];
        __syncthreads();
    }
    float inv = 1.f / red[0];

    for (int v = tid; v < VV; v += 1024) {
        float y = row[v] * scale + shift + bb[v];
        beta[(size_t)k * VV + v] = expf(y - mx) * inv;
    }
}

// ---------------- launch -----------------------------------------------------
extern "C" void kernel_launch(void* const* d_in, const int* in_sizes, int n_in,
                              void* d_out, int out_size)
{
    const float* input_   = (const float*)d_in[0];
    const float* eps      = (const float*)d_in[2];
    const float* en1_W    = (const float*)d_in[3];
    const float* en1_b    = (const float*)d_in[4];
    const float* en2_W    = (const float*)d_in[5];
    const float* en2_b    = (const float*)d_in[6];
    const float* mean_W   = (const float*)d_in[7];
    const float* mean_b   = (const float*)d_in[8];
    const float* logvar_W = (const float*)d_in[9];
    const float* logvar_b = (const float*)d_in[10];
    const float* mu1_W    = (const float*)d_in[11];
    const float* mu1_b    = (const float*)d_in[12];
    const float* mu2_W    = (const float*)d_in[13];
    const float* mu2_b    = (const float*)d_in[14];
    const float* mu_W     = (const float*)d_in[15];
    const float* mu_b     = (const float*)d_in[16];
    const float* topics   = (const float*)d_in[17];
    const float* bbias    = (const float*)d_in[18];
    const float* emb      = (const float*)d_in[19];
    const float* g_mean   = (const float*)d_in[20];
    const float* b_mean   = (const float*)d_in[21];
    const float* g_logvar = (const float*)d_in[22];
    const float* b_logvar = (const float*)d_in[23];
    const float* g_x      = (const float*)d_in[24];
    const float* b_x      = (const float*)d_in[25];
    const float* g_phi    = (const float*)d_in[26];
    const float* b_phi    = (const float*)d_in[27];
    const float* g_dec    = (const float*)d_in[28];
    const float* b_dec    = (const float*)d_in[29];

    float* out = (float*)d_out;
    float* out_z     = out;
    float* out_recon = out + (long long)NB * CC;
    float* out_zx    = out_recon + (long long)NB * VV;
    float* out_zc    = out_zx + (long long)NB * CC;
    float* out_theta = out_zc + (long long)KK * CC;

    void* sp = nullptr;
    cudaGetSymbolAddress(&sp, g_scratch);
    float* S = (float*)sp;
    float* s_en1    = S + OFF_EN1;
    float* s_en2    = S + OFF_EN2;
    float* s_pm     = S + OFF_PM;
    float* s_lv     = S + OFF_LV;
    float* s_z      = S + OFF_Z;
    float* s_zx     = S + OFF_ZX;
    float* s_zc     = S + OFF_ZC;
    float* s_theta  = S + OFF_THETA;
    float* s_mu1    = S + OFF_MU1;
    float* s_mu2    = S + OFF_MU2;
    float* s_muz    = S + OFF_MUZ;
    float* s_logits = S + OFF_LOGITS;
    float* s_beta   = S + OFF_BETA;
    float* st_pm    = S + OFF_SPM;
    float* st_lv    = S + OFF_SLV;
    float* st_z     = S + OFF_SZ;
    float* st_t     = S + OFF_ST;

    cudaFuncSetAttribute(gemm1_i8, cudaFuncAttributeMaxDynamicSharedMemorySize, G1_SMEM);
    cudaFuncSetAttribute(gemm_nt_bf16x3<true, true, false>,
                         cudaFuncAttributeMaxDynamicSharedMemorySize, NTB_SMEM);
    cudaFuncSetAttribute(gemm_nt_bf16x3<false, false, true>,
                         cudaFuncAttributeMaxDynamicSharedMemorySize, NTB_SMEM);

    // 0) quantize input + en1_W to 2-digit s8
    quantize_rows<<<NB + E1, 256>>>(input_, en1_W);

    // 1-4) decoder-side small kernels (independent of encoder)
    colstats_kernel<<<2, 256>>>(topics, KK, st_t);
    bn_apply_kernel<<<(KK * CC + 255) / 256, 256>>>(topics, st_t, g_phi, b_phi, KK * CC, s_zc, out_zc);
    mu1_kernel<<<(KK * 100 + 255) / 256, 256>>>(s_zc, mu1_W, mu1_b, s_mu1);
    mu2_kernel<<<KK, 128>>>(s_mu1, mu2_W, mu2_b, s_mu2);

    // 5) en1 = softplus(input @ en1_W^T + b) — int8 x3 tensor cores
    gemm1_i8<<<dim3(E1 / 128, NB / 128), 512, G1_SMEM>>>(en1_b, s_en1);

    // 6) muz
    muz_kernel<<<KK, 128>>>(s_mu2, mu_W, mu_b, s_muz);

    // 7) en2 — bf16x3 tensor cores
    gemm_nt_bf16x3<true, true, false><<<dim3(E2 / 128, NB / 128), 512, NTB_SMEM>>>(
        s_en1, en2_W, en2_b, s_en2, NB, E2, E1);

    // 8) heads
    meanlogvar_kernel<<<(NB * 4 + 255) / 256, 256>>>(
        s_en2, mean_W, mean_b, logvar_W, logvar_b, s_pm, s_lv);

    // 9-11) BN stats + z
    colstats_kernel<<<2, 256>>>(s_pm, NB, st_pm);
    colstats_kernel<<<2, 256>>>(s_lv, NB, st_lv);
    z_kernel<<<(NB * CC + 255) / 256, 256>>>(
        s_pm, s_lv, st_pm, st_lv, g_mean, b_mean, g_logvar, b_logvar, eps, s_z, out_z);

    // 12-13) zx
    colstats_kernel<<<2, 256>>>(s_z, NB, st_z);
    bn_apply_kernel<<<(NB * CC + 255) / 256, 256>>>(s_z, st_z, g_x, b_x, NB * CC, s_zx, out_zx);

    // 14) theta
    theta_kernel<<<NB, 256>>>(s_zx, s_zc, s_theta, out_theta);

    // 15) logits = mu_z @ emb^T — bf16x3
    gemm_nt_bf16x3<false, false, true><<<dim3((VV + 127) / 128, (KK + 127) / 128), 512, NTB_SMEM>>>(
        s_muz, emb, nullptr, s_logits, KK, VV, EMB);

    // 16) beta
    beta_kernel<<<KK, 1024>>>(s_logits, bbias, g_dec, b_dec, s_beta);

    // 17) recon = theta @ beta
    recon_tf32<<<dim3((VV + 127) / 128, NB / 128), 256>>>(s_theta, s_beta, out_recon);

    (void)in_sizes; (void)n_in; (void)out_size;
}

// round 6
// speedup vs baseline: 1.9123x; 1.9123x over previous
#include <cuda_runtime.h>
#include <cuda_bf16.h>
#include <math.h>
#include <float.h>
#include <stdint.h>

// ---------------- problem dims ----------------
#define NB   2048
#define VV   50000
#define E1   1024
#define E2   512
#define CC   2
#define KK   200
#define EMB  300

#define KP   50048              // VV padded to multiple of 32
#define KPW  (KP/2)             // 25024 words per row
#define G1NT (KP / 32)          // 1564 k-tiles

// ---------------- float scratch ----------------------------------------------
#define OFF_EN1    0LL
#define OFF_EN2    (OFF_EN1 + (long long)NB*E1)
#define OFF_PM     (OFF_EN2 + (long long)NB*E2)
#define OFF_LV     (OFF_PM + (long long)NB*CC)
#define OFF_Z      (OFF_LV + (long long)NB*CC)
#define OFF_ZX     (OFF_Z + (long long)NB*CC)
#define OFF_ZC     (OFF_ZX + (long long)NB*CC)
#define OFF_THETA  (OFF_ZC + (long long)KK*CC)
#define OFF_MU1    (OFF_THETA + (long long)NB*KK)
#define OFF_MU2    (OFF_MU1 + (long long)KK*100)
#define OFF_MUZ    (OFF_MU2 + (long long)KK*100)
#define OFF_LOGITS (OFF_MUZ + (long long)KK*EMB)
#define OFF_BETA   (OFF_LOGITS + (long long)KK*VV)
#define OFF_SPM    (OFF_BETA + (long long)KK*VV)
#define OFF_SLV    (OFF_SPM + 4)
#define OFF_SZ     (OFF_SLV + 4)
#define OFF_ST     (OFF_SZ + 4)
#define SCRATCH_FLOATS (OFF_ST + 8)

__device__ float g_scratch[SCRATCH_FLOATS];

// ---------------- bf16 hi/lo planes (words) -----------------------------------
#define WA 51249152LL           // NB * KPW
#define WB 25624576LL           // E1 * KPW
#define W_AH 0LL
#define W_AL (W_AH + WA)
#define W_BH (W_AL + WA)
#define W_BL (W_BH + WB)

__device__ __align__(16) uint32_t g_bf[2*WA + 2*WB];

__device__ __forceinline__ float softplusf(float x) {
    return fmaxf(x, 0.0f) + log1pf(expf(-fabsf(x)));
}

__device__ __forceinline__ uint32_t pk_bf16(float lo, float hi) {
    uint32_t r;
    asm("cvt.rn.bf16x2.f32 %0, %1, %2;" : "=r"(r) : "f"(hi), "f"(lo));
    return r;
}

__device__ __forceinline__ void mma_bf16(float* d,
                                         uint32_t a0, uint32_t a1, uint32_t a2, uint32_t a3,
                                         uint32_t b0, uint32_t b1)
{
    asm volatile(
        "mma.sync.aligned.m16n8k16.row.col.f32.bf16.bf16.f32 "
        "{%0,%1,%2,%3},{%4,%5,%6,%7},{%8,%9},{%0,%1,%2,%3};"
        : "+f"(d[0]), "+f"(d[1]), "+f"(d[2]), "+f"(d[3])
        : "r"(a0), "r"(a1), "r"(a2), "r"(a3), "r"(b0), "r"(b1));
}

// =============================================================================
// Pre-pass: split input (2048 rows) and en1_W (1024 rows) into bf16 hi/lo
// planes, rows padded to KP with zeros. word w = elements (2w lo-half, 2w+1 hi).
// =============================================================================
__global__ void __launch_bounds__(256)
split_bf16(const float* __restrict__ A, const float* __restrict__ B)
{
    const int b = blockIdx.x, tid = threadIdx.x;
    const float* src;
    uint32_t *h, *l;
    if (b < NB) {
        src = A + (size_t)b * VV;
        h = g_bf + W_AH + (size_t)b * KPW;
        l = g_bf + W_AL + (size_t)b * KPW;
    } else {
        int r = b - NB;
        src = B + (size_t)r * VV;
        h = g_bf + W_BH + (size_t)r * KPW;
        l = g_bf + W_BL + (size_t)r * KPW;
    }
    for (int i = tid; i < VV / 4; i += 256) {
        float4 v = *reinterpret_cast<const float4*>(src + i * 4);
        __nv_bfloat16 hx = __float2bfloat16_rn(v.x), hy = __float2bfloat16_rn(v.y);
        __nv_bfloat16 hz = __float2bfloat16_rn(v.z), hw = __float2bfloat16_rn(v.w);
        h[2*i]     = ((uint32_t)__bfloat16_as_ushort(hy) << 16) | __bfloat16_as_ushort(hx);
        h[2*i + 1] = ((uint32_t)__bfloat16_as_ushort(hw) << 16) | __bfloat16_as_ushort(hz);
        l[2*i]     = pk_bf16(v.x - __bfloat162float(hx), v.y - __bfloat162float(hy));
        l[2*i + 1] = pk_bf16(v.z - __bfloat162float(hz), v.w - __bfloat162float(hw));
    }
    if (tid < KPW - VV/2) {           // zero pad words [25000, 25024)
        h[VV/2 + tid] = 0u;
        l[VV/2 + tid] = 0u;
    }
}

// =============================================================================
// GEMM1: en1 = softplus(input @ en1_W^T + b), 3xbf16 from pre-split planes.
// 128x128 tile, BK=32, 512 threads (16 warps, 32x32 warp tiles),
// 3-stage cp.async pipeline. Plane: 128 rows x 80B (64B data + 16B pad).
// =============================================================================
#define PL    10240                      // plane bytes
#define PLW   2560                       // plane words
#define BUFW  (4 * PLW)                  // buffer words (Ah,Al,Bh,Bl)
#define G1_SMEM (3 * 4 * PL)             // 122880 B

__global__ void __launch_bounds__(512, 1)
gemm1_pre(const float* __restrict__ bias, float* __restrict__ C)
{
    extern __shared__ __align__(16) uint32_t sw[];
    const uint32_t sb32 = (uint32_t)__cvta_generic_to_shared(sw);
    const int tid = threadIdx.x;
    const int lane = tid & 31, warp = tid >> 5;
    const int gid = lane >> 2, tig = lane & 3;
    const int wm = warp >> 2, wn = warp & 3;
    const int m0 = blockIdx.y * 128, n0 = blockIdx.x * 128;

    float acc[2][4][4];
#pragma unroll
    for (int i = 0; i < 2; i++)
#pragma unroll
        for (int j = 0; j < 4; j++)
#pragma unroll
            for (int l = 0; l < 4; l++) acc[i][j][l] = 0.0f;

    const int row = tid >> 2, part = tid & 3;     // 128 rows x 4 16B-chunks
    const uint32_t* gAh = g_bf + W_AH + (size_t)(m0 + row) * KPW + part * 4;
    const uint32_t* gAl = g_bf + W_AL + (size_t)(m0 + row) * KPW + part * 4;
    const uint32_t* gBh = g_bf + W_BH + (size_t)(n0 + row) * KPW + part * 4;
    const uint32_t* gBl = g_bf + W_BL + (size_t)(n0 + row) * KPW + part * 4;
    const uint32_t sdst = sb32 + (uint32_t)(row * 80 + part * 16);

    auto issue = [&](int t) {
        const uint32_t boff = (uint32_t)(t % 3) * (4 * PL);
        const size_t k = (size_t)t * 16;          // words per tile
        asm volatile("cp.async.cg.shared.global [%0], [%1], 16;"
                     :: "r"(sdst + boff), "l"(gAh + k) : "memory");
        asm volatile("cp.async.cg.shared.global [%0], [%1], 16;"
                     :: "r"(sdst + boff + PL), "l"(gAl + k) : "memory");
        asm volatile("cp.async.cg.shared.global [%0], [%1], 16;"
                     :: "r"(sdst + boff + 2 * PL), "l"(gBh + k) : "memory");
        asm volatile("cp.async.cg.shared.global [%0], [%1], 16;"
                     :: "r"(sdst + boff + 3 * PL), "l"(gBl + k) : "memory");
        asm volatile("cp.async.commit_group;" ::: "memory");
    };

    issue(0);
    issue(1);

    for (int t = 0; t < G1NT; t++) {
        if (t == G1NT - 1) asm volatile("cp.async.wait_group 0;" ::: "memory");
        else               asm volatile("cp.async.wait_group 1;" ::: "memory");
        __syncthreads();
        if (t + 2 < G1NT) issue(t + 2);

        const uint32_t* bb = sw + (size_t)(t % 3) * BUFW;
#pragma unroll
        for (int kkw = 0; kkw < 16; kkw += 8) {
            uint32_t ah[2][4], al[2][4], bh[4][2], bl[4][2];
#pragma unroll
            for (int ms = 0; ms < 2; ms++) {
                int base = (wm * 32 + ms * 16 + gid) * 20 + kkw + tig;
                ah[ms][0] = bb[base];          ah[ms][1] = bb[base + 160];
                ah[ms][2] = bb[base + 4];      ah[ms][3] = bb[base + 164];
                al[ms][0] = bb[base + PLW];         al[ms][1] = bb[base + PLW + 160];
                al[ms][2] = bb[base + PLW + 4];     al[ms][3] = bb[base + PLW + 164];
            }
#pragma unroll
            for (int ns = 0; ns < 4; ns++) {
                int base = 2 * PLW + (wn * 32 + ns * 8 + gid) * 20 + kkw + tig;
                bh[ns][0] = bb[base];          bh[ns][1] = bb[base + 4];
                bl[ns][0] = bb[base + PLW];    bl[ns][1] = bb[base + PLW + 4];
            }
#pragma unroll
            for (int ms = 0; ms < 2; ms++)
#pragma unroll
                for (int ns = 0; ns < 4; ns++) {
                    mma_bf16(acc[ms][ns], ah[ms][0], ah[ms][1], ah[ms][2], ah[ms][3],
                             bh[ns][0], bh[ns][1]);
                    mma_bf16(acc[ms][ns], ah[ms][0], ah[ms][1], ah[ms][2], ah[ms][3],
                             bl[ns][0], bl[ns][1]);
                    mma_bf16(acc[ms][ns], al[ms][0], al[ms][1], al[ms][2], al[ms][3],
                             bh[ns][0], bh[ns][1]);
                }
        }
    }

#pragma unroll
    for (int ms = 0; ms < 2; ms++) {
        const int r0 = m0 + wm * 32 + ms * 16 + gid;
#pragma unroll
        for (int ns = 0; ns < 4; ns++) {
            const int c0 = n0 + wn * 32 + ns * 8 + 2 * tig;
            const float bv0 = bias[c0], bv1 = bias[c0 + 1];
            C[(size_t)r0 * E1 + c0]           = softplusf(acc[ms][ns][0] + bv0);
            C[(size_t)r0 * E1 + c0 + 1]       = softplusf(acc[ms][ns][1] + bv1);
            C[(size_t)(r0 + 8) * E1 + c0]     = softplusf(acc[ms][ns][2] + bv0);
            C[(size_t)(r0 + 8) * E1 + c0 + 1] = softplusf(acc[ms][ns][3] + bv1);
        }
    }
}

// ============================ bf16x3 NT GEMM (en2 + logits) ==================
#define NTB_SMEM (2 * 10240 * 4)

template<bool SP, bool HB, bool CHKMN>
__global__ void __launch_bounds__(512, 1)
gemm_nt_bf16x3(const float* __restrict__ A, const float* __restrict__ B,
               const float* __restrict__ bias, float* __restrict__ C,
               int M, int N, int K)
{
    extern __shared__ __align__(16) uint32_t sw[];
    const int tid = threadIdx.x;
    const int lane = tid & 31, warp = tid >> 5;
    const int gid = lane >> 2, tig = lane & 3;
    const int wm = warp >> 2, wn = warp & 3;
    const int m0 = blockIdx.y * 128, n0 = blockIdx.x * 128;
    const int nt = (K + 31) / 32;

    float acc[2][4][4];
#pragma unroll
    for (int i = 0; i < 2; i++)
#pragma unroll
        for (int j = 0; j < 4; j++)
#pragma unroll
            for (int l = 0; l < 4; l++) acc[i][j][l] = 0.0f;

    const int srow = tid >> 3;
    const int sq   = tid & 7;
    float4 stA[2], stB[2];

    auto load_tile = [&](int t) {
        const int gk = t * 32 + sq * 4;
#pragma unroll
        for (int l = 0; l < 2; l++) {
            int r = srow + l * 64;
            {
                int gm = m0 + r;
                float4 v = make_float4(0.f, 0.f, 0.f, 0.f);
                if (((!CHKMN) || gm < M)) {
                    if (gk + 3 < K) v = *reinterpret_cast<const float4*>(A + (size_t)gm * K + gk);
                    else if (gk < K) {
                        const float* p = A + (size_t)gm * K;
                        v.x = p[gk];
                        if (gk + 1 < K) v.y = p[gk + 1];
                        if (gk + 2 < K) v.z = p[gk + 2];
                    }
                }
                stA[l] = v;
            }
            {
                int gn = n0 + r;
                float4 v = make_float4(0.f, 0.f, 0.f, 0.f);
                if (((!CHKMN) || gn < N)) {
                    if (gk + 3 < K) v = *reinterpret_cast<const float4*>(B + (size_t)gn * K + gk);
                    else if (gk < K) {
                        const float* p = B + (size_t)gn * K;
                        v.x = p[gk];
                        if (gk + 1 < K) v.y = p[gk + 1];
                        if (gk + 2 < K) v.z = p[gk + 2];
                    }
                }
                stB[l] = v;
            }
        }
    };

    auto store_tile = [&](uint32_t* buf) {
#pragma unroll
        for (int l = 0; l < 2; l++) {
            int r = srow + l * 64;
            uint32_t w = (uint32_t)(r * 20 + sq * 2);
            {
                float4 v = stA[l];
                __nv_bfloat16 hx = __float2bfloat16_rn(v.x), hy = __float2bfloat16_rn(v.y);
                __nv_bfloat16 hz = __float2bfloat16_rn(v.z), hw = __float2bfloat16_rn(v.w);
                buf[w]     = ((uint32_t)__bfloat16_as_ushort(hy) << 16) | __bfloat16_as_ushort(hx);
                buf[w + 1] = ((uint32_t)__bfloat16_as_ushort(hw) << 16) | __bfloat16_as_ushort(hz);
                buf[w + 2560]     = pk_bf16(v.x - __bfloat162float(hx), v.y - __bfloat162float(hy));
                buf[w + 2560 + 1] = pk_bf16(v.z - __bfloat162float(hz), v.w - __bfloat162float(hw));
            }
            {
                float4 v = stB[l];
                __nv_bfloat16 hx = __float2bfloat16_rn(v.x), hy = __float2bfloat16_rn(v.y);
                __nv_bfloat16 hz = __float2bfloat16_rn(v.z), hw = __float2bfloat16_rn(v.w);
                buf[w + 5120]     = ((uint32_t)__bfloat16_as_ushort(hy) << 16) | __bfloat16_as_ushort(hx);
                buf[w + 5120 + 1] = ((uint32_t)__bfloat16_as_ushort(hw) << 16) | __bfloat16_as_ushort(hz);
                buf[w + 7680]     = pk_bf16(v.x - __bfloat162float(hx), v.y - __bfloat162float(hy));
                buf[w + 7680 + 1] = pk_bf16(v.z - __bfloat162float(hz), v.w - __bfloat162float(hw));
            }
        }
    };

    load_tile(0);
    store_tile(sw);
    __syncthreads();

    for (int t = 0; t < nt; t++) {
        const int b = t & 1;
        uint32_t* bb = sw + b * 10240;
        if (t + 1 < nt) load_tile(t + 1);

#pragma unroll
        for (int kkw = 0; kkw < 16; kkw += 8) {
            uint32_t ah[2][4], al[2][4], bh[4][2], bl[4][2];
#pragma unroll
            for (int ms = 0; ms < 2; ms++) {
                int base = (wm * 32 + ms * 16 + gid) * 20 + kkw + tig;
                ah[ms][0] = bb[base];       ah[ms][1] = bb[base + 160];
                ah[ms][2] = bb[base + 4];   ah[ms][3] = bb[base + 164];
                al[ms][0] = bb[base + 2560];       al[ms][1] = bb[base + 2560 + 160];
                al[ms][2] = bb[base + 2560 + 4];   al[ms][3] = bb[base + 2560 + 164];
            }
#pragma unroll
            for (int ns = 0; ns < 4; ns++) {
                int base = 5120 + (wn * 32 + ns * 8 + gid) * 20 + kkw + tig;
                bh[ns][0] = bb[base];       bh[ns][1] = bb[base + 4];
                bl[ns][0] = bb[base + 2560]; bl[ns][1] = bb[base + 2560 + 4];
            }
#pragma unroll
            for (int ms = 0; ms < 2; ms++)
#pragma unroll
                for (int ns = 0; ns < 4; ns++) {
                    mma_bf16(acc[ms][ns], ah[ms][0], ah[ms][1], ah[ms][2], ah[ms][3],
                             bh[ns][0], bh[ns][1]);
                    mma_bf16(acc[ms][ns], ah[ms][0], ah[ms][1], ah[ms][2], ah[ms][3],
                             bl[ns][0], bl[ns][1]);
                    mma_bf16(acc[ms][ns], al[ms][0], al[ms][1], al[ms][2], al[ms][3],
                             bh[ns][0], bh[ns][1]);
                }
        }

        if (t + 1 < nt) store_tile(sw + (b ^ 1) * 10240);
        __syncthreads();
    }

#pragma unroll
    for (int ms = 0; ms < 2; ms++) {
        int r0 = m0 + wm * 32 + ms * 16 + gid;
#pragma unroll
        for (int ns = 0; ns < 4; ns++) {
            int c0 = n0 + wn * 32 + ns * 8 + 2 * tig;
            float bv0 = 0.f, bv1 = 0.f;
            if (HB) { bv0 = bias[c0]; bv1 = bias[c0 + 1]; }
            float v00 = acc[ms][ns][0] + bv0;
            float v01 = acc[ms][ns][1] + bv1;
            float v10 = acc[ms][ns][2] + bv0;
            float v11 = acc[ms][ns][3] + bv1;
            if (SP) { v00 = softplusf(v00); v01 = softplusf(v01);
                      v10 = softplusf(v10); v11 = softplusf(v11); }
            if (!CHKMN) {
                C[(size_t)r0 * N + c0]           = v00;
                C[(size_t)r0 * N + c0 + 1]       = v01;
                C[(size_t)(r0 + 8) * N + c0]     = v10;
                C[(size_t)(r0 + 8) * N + c0 + 1] = v11;
            } else {
                if (r0 < M) {
                    if (c0 < N)     C[(size_t)r0 * N + c0]     = v00;
                    if (c0 + 1 < N) C[(size_t)r0 * N + c0 + 1] = v01;
                }
                if (r0 + 8 < M) {
                    if (c0 < N)     C[(size_t)(r0 + 8) * N + c0]     = v10;
                    if (c0 + 1 < N) C[(size_t)(r0 + 8) * N + c0 + 1] = v11;
                }
            }
        }
    }
}

// ============================ tf32 recon =====================================
__device__ __forceinline__ unsigned tf32_rna(float x) {
    unsigned r;
    asm("cvt.rna.tf32.f32 %0, %1;" : "=r"(r) : "f"(x));
    return r;
}

__device__ __forceinline__ void mma_tf32(float* d,
                                         unsigned a0, unsigned a1, unsigned a2, unsigned a3,
                                         unsigned b0, unsigned b1)
{
    asm volatile(
        "mma.sync.aligned.m16n8k8.row.col.f32.tf32.tf32.f32 "
        "{%0,%1,%2,%3},{%4,%5,%6,%7},{%8,%9},{%0,%1,%2,%3};"
        : "+f"(d[0]), "+f"(d[1]), "+f"(d[2]), "+f"(d[3])
        : "r"(a0), "r"(a1), "r"(a2), "r"(a3), "r"(b0), "r"(b1));
}

__global__ void __launch_bounds__(256, 2)
recon_tf32(const float* __restrict__ A, const float* __restrict__ B,
           float* __restrict__ C)
{
    __shared__ float Ah[128][20];
    __shared__ float Bh[16][136];
    const int tid = threadIdx.x;
    const int lane = tid & 31, warp = tid >> 5;
    const int gid = lane >> 2, tig = lane & 3;
    const int wm = warp >> 1, wn = warp & 1;
    const int m0 = blockIdx.y * 128;
    const int n0 = blockIdx.x * 128;

    float acc[2][8][4];
#pragma unroll
    for (int i = 0; i < 2; i++)
#pragma unroll
        for (int j = 0; j < 8; j++)
#pragma unroll
            for (int l = 0; l < 4; l++) acc[i][j][l] = 0.0f;

    for (int k0 = 0; k0 < KK; k0 += 16) {
#pragma unroll
        for (int l = 0; l < 2; l++) {
            int idx = tid + l * 256;
            int row = idx >> 2, kq = (idx & 3) * 4;
            int gk = k0 + kq;
            float4 v = make_float4(0.f, 0.f, 0.f, 0.f);
            if (gk + 3 < KK)
                v = *reinterpret_cast<const float4*>(A + (size_t)(m0 + row) * KK + gk);
            Ah[row][kq + 0] = __uint_as_float(tf32_rna(v.x));
            Ah[row][kq + 1] = __uint_as_float(tf32_rna(v.y));
            Ah[row][kq + 2] = __uint_as_float(tf32_rna(v.z));
            Ah[row][kq + 3] = __uint_as_float(tf32_rna(v.w));
        }
#pragma unroll
        for (int l = 0; l < 2; l++) {
            int idx = tid + l * 256;
            int kk = idx >> 5, nc = (idx & 31) * 4;
            int gk = k0 + kk, gn = n0 + nc;
            float4 v = make_float4(0.f, 0.f, 0.f, 0.f);
            if (gk < KK && gn + 3 < VV)
                v = *reinterpret_cast<const float4*>(B + (size_t)gk * VV + gn);
            Bh[kk][nc + 0] = __uint_as_float(tf32_rna(v.x));
            Bh[kk][nc + 1] = __uint_as_float(tf32_rna(v.y));
            Bh[kk][nc + 2] = __uint_as_float(tf32_rna(v.z));
            Bh[kk][nc + 3] = __uint_as_float(tf32_rna(v.w));
        }
        __syncthreads();

#pragma unroll
        for (int kk = 0; kk < 16; kk += 8) {
            unsigned a[2][4], b[8][2];
#pragma unroll
            for (int ms = 0; ms < 2; ms++) {
                int r = wm * 32 + ms * 16 + gid;
                a[ms][0] = __float_as_uint(Ah[r][kk + tig]);
                a[ms][1] = __float_as_uint(Ah[r + 8][kk + tig]);
                a[ms][2] = __float_as_uint(Ah[r][kk + tig + 4]);
                a[ms][3] = __float_as_uint(Ah[r + 8][kk + tig + 4]);
            }
#pragma unroll
            for (int ns = 0; ns < 8; ns++) {
                int n = wn * 64 + ns * 8 + gid;
                b[ns][0] = __float_as_uint(Bh[kk + tig][n]);
                b[ns][1] = __float_as_uint(Bh[kk + tig + 4][n]);
            }
#pragma unroll
            for (int ms = 0; ms < 2; ms++)
#pragma unroll
                for (int ns = 0; ns < 8; ns++)
                    mma_tf32(acc[ms][ns], a[ms][0], a[ms][1], a[ms][2], a[ms][3],
                             b[ns][0], b[ns][1]);
        }
        __syncthreads();
    }

#pragma unroll
    for (int ms = 0; ms < 2; ms++) {
        int r0 = m0 + wm * 32 + ms * 16 + gid;
#pragma unroll
        for (int ns = 0; ns < 8; ns++) {
            int c0 = n0 + wn * 64 + ns * 8 + 2 * tig;
            if (c0 < VV) {
                C[(size_t)r0 * VV + c0]       = acc[ms][ns][0];
                C[(size_t)(r0 + 8) * VV + c0] = acc[ms][ns][2];
            }
            if (c0 + 1 < VV) {
                C[(size_t)r0 * VV + c0 + 1]       = acc[ms][ns][1];
                C[(size_t)(r0 + 8) * VV + c0 + 1] = acc[ms][ns][3];
            }
        }
    }
}

// ---------------- mean / logvar heads ---------------------------------------
__global__ void meanlogvar_kernel(const float* __restrict__ en2,
                                  const float* __restrict__ mW, const float* __restrict__ mb,
                                  const float* __restrict__ lW, const float* __restrict__ lb,
                                  float* __restrict__ pm, float* __restrict__ lv)
{
    int t = blockIdx.x * blockDim.x + threadIdx.x;
    if (t >= NB * 4) return;
    int n = t >> 2, j = t & 3;
    const float* w = (j < 2) ? (mW + j * E2) : (lW + (j - 2) * E2);
    const float* x = en2 + (size_t)n * E2;
    float s = 0.f;
    for (int i = 0; i < E2; i += 4) {
        float4 xa = *reinterpret_cast<const float4*>(x + i);
        float4 wa = *reinterpret_cast<const float4*>(w + i);
        s += xa.x * wa.x + xa.y * wa.y + xa.z * wa.z + xa.w * wa.w;
    }
    if (j < 2) pm[n * 2 + j] = s + mb[j];
    else       lv[n * 2 + (j - 2)] = s + lb[j - 2];
}

// ---------------- column stats of (R x 2) -----------------------------------
__global__ void colstats_kernel(const float* __restrict__ X, int R, float* __restrict__ out)
{
    __shared__ float ss[256], s2[256];
    int c = blockIdx.x, tid = threadIdx.x;
    float s = 0.f, q = 0.f;
    for (int r = tid; r < R; r += 256) {
        float x = X[r * 2 + c];
        s += x; q += x * x;
    }
    ss[tid] = s; s2[tid] = q;
    __syncthreads();
    for (int st = 128; st > 0; st >>= 1) {
        if (tid < st) { ss[tid] += ss[tid + st]; s2[tid] += s2[tid + st]; }
        __syncthreads();
    }
    if (tid == 0) {
        float m = ss[0] / R;
        out[c] = m;
        out[2 + c] = s2[0] / R - m * m;
    }
}

// ---------------- z ----------------------------------------------------------
__global__ void z_kernel(const float* __restrict__ pm, const float* __restrict__ lv,
                         const float* __restrict__ spm, const float* __restrict__ slv,
                         const float* __restrict__ gm, const float* __restrict__ bm,
                         const float* __restrict__ gl, const float* __restrict__ bl,
                         const float* __restrict__ eps,
                         float* __restrict__ gz, float* __restrict__ outz)
{
    int idx = blockIdx.x * 256 + threadIdx.x;
    if (idx >= NB * CC) return;
    int c = idx & 1;
    float pmb = gm[c] * (pm[idx] - spm[c]) * rsqrtf(spm[2 + c] + 1e-5f) + bm[c];
    float lvb = gl[c] * (lv[idx] - slv[c]) * rsqrtf(slv[2 + c] + 1e-5f) + bl[c];
    float z = pmb + sqrtf(expf(lvb)) * eps[idx];
    gz[idx] = z;
    outz[idx] = z;
}

// ---------------- BN apply ---------------------------------------------------
__global__ void bn_apply_kernel(const float* __restrict__ X, const float* __restrict__ stats,
                                const float* __restrict__ g, const float* __restrict__ b,
                                int total, float* __restrict__ o1, float* __restrict__ o2)
{
    int idx = blockIdx.x * 256 + threadIdx.x;
    if (idx >= total) return;
    int c = idx & 1;
    float y = g[c] * (X[idx] - stats[c]) * rsqrtf(stats[2 + c] + 1e-5f) + b[c];
    o1[idx] = y;
    o2[idx] = y;
}

// ---------------- theta ------------------------------------------------------
__global__ void theta_kernel(const float* __restrict__ zx, const float* __restrict__ zc,
                             float* __restrict__ gtheta, float* __restrict__ otheta)
{
    __shared__ float sz[KK * 2];
    __shared__ float red[256];
    int n = blockIdx.x, tid = threadIdx.x;
    for (int i = tid; i < KK * 2; i += 256) sz[i] = zc[i];
    __syncthreads();
    float x0 = zx[n * 2], x1 = zx[n * 2 + 1];
    float l = -FLT_MAX;
    if (tid < KK) {
        float dx = x0 - sz[tid * 2];
        float dy = x1 - sz[tid * 2 + 1];
        l = -0.5f * (dx * dx + dy * dy);
    }
    red[tid] = l;
    __syncthreads();
    for (int st = 128; st > 0; st >>= 1) {
        if (tid < st) red[tid] = fmaxf(red[tid], red[tid + st]);
        __syncthreads();
    }
    float mx = red[0];
    __syncthreads();
    float e = (tid < KK) ? expf(l - mx) : 0.f;
    red[tid] = e;
    __syncthreads();
    for (int st = 128; st > 0; st >>= 1) {
        if (tid < st) red[tid] += red[tid + st];
        __syncthreads();
    }
    float inv = 1.f / red[0];
    if (tid < KK) {
        float th = e * inv;
        gtheta[(size_t)n * KK + tid] = th;
        otheta[(size_t)n * KK + tid] = th;
    }
}

// ---------------- decoder MLP ------------------------------------------------
__global__ void mu1_kernel(const float* __restrict__ zc, const float* __restrict__ W,
                           const float* __restrict__ b, float* __restrict__ out)
{
    int t = blockIdx.x * 256 + threadIdx.x;
    if (t >= KK * 100) return;
    int k = t / 100, j = t % 100;
    float v = zc[k * 2] * W[j * 2] + zc[k * 2 + 1] * W[j * 2 + 1] + b[j];
    out[t] = softplusf(v);
}

__global__ void mu2_kernel(const float* __restrict__ mu1, const float* __restrict__ W,
                           const float* __restrict__ b, float* __restrict__ out)
{
    __shared__ float row[100];
    int k = blockIdx.x, tid = threadIdx.x;
    if (tid < 100) row[tid] = mu1[k * 100 + tid];
    __syncthreads();
    if (tid < 100) {
        const float* w = W + tid * 100;
        float s = b[tid];
        for (int i = 0; i < 100; i++) s += row[i] * w[i];
        out[k * 100 + tid] = softplusf(s);
    }
}

__global__ void muz_kernel(const float* __restrict__ mu2, const float* __restrict__ W,
                           const float* __restrict__ b, float* __restrict__ out)
{
    __shared__ float row[100];
    int k = blockIdx.x, tid = threadIdx.x;
    if (tid < 100) row[tid] = mu2[k * 100 + tid];
    __syncthreads();
    for (int j = tid; j < EMB; j += 128) {
        const float* w = W + j * 100;
        float s = b[j];
        for (int i = 0; i < 100; i++) s += row[i] * w[i];
        out[k * EMB + j] = s;
    }
}

// ---------------- beta -------------------------------------------------------
__global__ void __launch_bounds__(1024)
beta_kernel(const float* __restrict__ logits, const float* __restrict__ bbias,
            const float* __restrict__ gdec, const float* __restrict__ bdec,
            float* __restrict__ beta)
{
    __shared__ float red[1024];
    __shared__ float red2[1024];
    const int k = blockIdx.x, tid = threadIdx.x;
    const float* row = logits + (size_t)k * VV;
    const float* bb  = bbias + (size_t)k * VV;

    float s = 0.f, q = 0.f;
    for (int v = tid; v < VV; v += 1024) { float x = row[v]; s += x; q += x * x; }
    red[tid] = s; red2[tid] = q;
    __syncthreads();
    for (int st = 512; st > 0; st >>= 1) {
        if (tid < st) { red[tid] += red[tid + st]; red2[tid] += red2[tid + st]; }
        __syncthreads();
    }
    float mean = red[0] / VV;
    float var  = red2[0] / VV - mean * mean;
    float scale = gdec[k] * rsqrtf(var + 1e-5f);
    float shift = bdec[k] - mean * scale;
    __syncthreads();

    float mx = -FLT_MAX;
    for (int v = tid; v < VV; v += 1024) {
        float y = row[v] * scale + shift + bb[v];
        mx = fmaxf(mx, y);
    }
    red[tid] = mx;
    __syncthreads();
    for (int st = 512; st > 0; st >>= 1) {
        if (tid < st) red[tid] = fmaxf(red[tid], red[tid + st]);
        __syncthreads();
    }
    mx = red[0];
    __syncthreads();

    float se = 0.f;
    for (int v = tid; v < VV; v += 1024) {
        float y = row[v] * scale + shift + bb[v];
        se += expf(y - mx);
    }
    red[tid] = se;
    __syncthreads();
    for (int st = 512; st > 0; st >>= 1) {
        if (tid < st) red[tid] += red[tid + st];
        __syncthreads();
    }
    float inv = 1.f / red[0];

    for (int v = tid; v < VV; v += 1024) {
        float y = row[v] * scale + shift + bb[v];
        beta[(size_t)k * VV + v] = expf(y - mx) * inv;
    }
}

// ---------------- launch -----------------------------------------------------
extern "C" void kernel_launch(void* const* d_in, const int* in_sizes, int n_in,
                              void* d_out, int out_size)
{
    const float* input_   = (const float*)d_in[0];
    const float* eps      = (const float*)d_in[2];
    const float* en1_W    = (const float*)d_in[3];
    const float* en1_b    = (const float*)d_in[4];
    const float* en2_W    = (const float*)d_in[5];
    const float* en2_b    = (const float*)d_in[6];
    const float* mean_W   = (const float*)d_in[7];
    const float* mean_b   = (const float*)d_in[8];
    const float* logvar_W = (const float*)d_in[9];
    const float* logvar_b = (const float*)d_in[10];
    const float* mu1_W    = (const float*)d_in[11];
    const float* mu1_b    = (const float*)d_in[12];
    const float* mu2_W    = (const float*)d_in[13];
    const float* mu2_b    = (const float*)d_in[14];
    const float* mu_W     = (const float*)d_in[15];
    const float* mu_b     = (const float*)d_in[16];
    const float* topics   = (const float*)d_in[17];
    const float* bbias    = (const float*)d_in[18];
    const float* emb      = (const float*)d_in[19];
    const float* g_mean   = (const float*)d_in[20];
    const float* b_mean   = (const float*)d_in[21];
    const float* g_logvar = (const float*)d_in[22];
    const float* b_logvar = (const float*)d_in[23];
    const float* g_x      = (const float*)d_in[24];
    const float* b_x      = (const float*)d_in[25];
    const float* g_phi    = (const float*)d_in[26];
    const float* b_phi    = (const float*)d_in[27];
    const float* g_dec    = (const float*)d_in[28];
    const float* b_dec    = (const float*)d_in[29];

    float* out = (float*)d_out;
    float* out_z     = out;
    float* out_recon = out + (long long)NB * CC;
    float* out_zx    = out_recon + (long long)NB * VV;
    float* out_zc    = out_zx + (long long)NB * CC;
    float* out_theta = out_zc + (long long)KK * CC;

    void* sp = nullptr;
    cudaGetSymbolAddress(&sp, g_scratch);
    float* S = (float*)sp;
    float* s_en1    = S + OFF_EN1;
    float* s_en2    = S + OFF_EN2;
    float* s_pm     = S + OFF_PM;
    float* s_lv     = S + OFF_LV;
    float* s_z      = S + OFF_Z;
    float* s_zx     = S + OFF_ZX;
    float* s_zc     = S + OFF_ZC;
    float* s_theta  = S + OFF_THETA;
    float* s_mu1    = S + OFF_MU1;
    float* s_mu2    = S + OFF_MU2;
    float* s_muz    = S + OFF_MUZ;
    float* s_logits = S + OFF_LOGITS;
    float* s_beta   = S + OFF_BETA;
    float* st_pm    = S + OFF_SPM;
    float* st_lv    = S + OFF_SLV;
    float* st_z     = S + OFF_SZ;
    float* st_t     = S + OFF_ST;

    cudaFuncSetAttribute(gemm1_pre, cudaFuncAttributeMaxDynamicSharedMemorySize, G1_SMEM);
    cudaFuncSetAttribute(gemm_nt_bf16x3<true, true, false>,
                         cudaFuncAttributeMaxDynamicSharedMemorySize, NTB_SMEM);
    cudaFuncSetAttribute(gemm_nt_bf16x3<false, false, true>,
                         cudaFuncAttributeMaxDynamicSharedMemorySize, NTB_SMEM);

    // 0) pre-split input + en1_W into bf16 hi/lo planes
    split_bf16<<<NB + E1, 256>>>(input_, en1_W);

    // 1-4) decoder-side small kernels (independent of encoder)
    colstats_kernel<<<2, 256>>>(topics, KK, st_t);
    bn_apply_kernel<<<(KK * CC + 255) / 256, 256>>>(topics, st_t, g_phi, b_phi, KK * CC, s_zc, out_zc);
    mu1_kernel<<<(KK * 100 + 255) / 256, 256>>>(s_zc, mu1_W, mu1_b, s_mu1);
    mu2_kernel<<<KK, 128>>>(s_mu1, mu2_W, mu2_b, s_mu2);

    // 5) en1 = softplus(input @ en1_W^T + b) — bf16x3 from pre-split planes
    gemm1_pre<<<dim3(E1 / 128, NB / 128), 512, G1_SMEM>>>(en1_b, s_en1);

    // 6) muz
    muz_kernel<<<KK, 128>>>(s_mu2, mu_W, mu_b, s_muz);

    // 7) en2 — bf16x3 (in-loop cvt, small K so fine)
    gemm_nt_bf16x3<true, true, false><<<dim3(E2 / 128, NB / 128), 512, NTB_SMEM>>>(
        s_en1, en2_W, en2_b, s_en2, NB, E2, E1);

    // 8) heads
    meanlogvar_kernel<<<(NB * 4 + 255) / 256, 256>>>(
        s_en2, mean_W, mean_b, logvar_W, logvar_b, s_pm, s_lv);

    // 9-11) BN stats + z
    colstats_kernel<<<2, 256>>>(s_pm, NB, st_pm);
    colstats_kernel<<<2, 256>>>(s_lv, NB, st_lv);
    z_kernel<<<(NB * CC + 255) / 256, 256>>>(
        s_pm, s_lv, st_pm, st_lv, g_mean, b_mean, g_logvar, b_logvar, eps, s_z, out_z);

    // 12-13) zx
    colstats_kernel<<<2, 256>>>(s_z, NB, st_z);
    bn_apply_kernel<<<(NB * CC + 255) / 256, 256>>>(s_z, st_z, g_x, b_x, NB * CC, s_zx, out_zx);

    // 14) theta
    theta_kernel<<<NB, 256>>>(s_zx, s_zc, s_theta, out_theta);

    // 15) logits = mu_z @ emb^T — bf16x3
    gemm_nt_bf16x3<false, false, true><<<dim3((VV + 127) / 128, (KK + 127) / 128), 512, NTB_SMEM>>>(
        s_muz, emb, nullptr, s_logits, KK, VV, EMB);

    // 16) beta
    beta_kernel<<<KK, 1024>>>(s_logits, bbias, g_dec, b_dec, s_beta);

    // 17) recon = theta @ beta
    recon_tf32<<<dim3((VV + 127) / 128, NB / 128), 256>>>(s_theta, s_beta, out_recon);

    (void)in_sizes; (void)n_in; (void)out_size;
}